// round 11
// baseline (speedup 1.0000x reference)
#include <cuda_runtime.h>
#include <cuda_bf16.h>
#include <mma.h>
#include <cstdint>

using namespace nvcuda;

#define B_   2
#define L_   2048
#define D_   1024
#define H_   16
#define DH_  64
#define M_   (B_*L_)          // 4096 rows
#define K2_  2048             // split-K (hi/lo interleaved)
#define SCALE 0.125f          // 1/sqrt(64)

// ---------------- scratch (static device memory; no allocs) ----------------
__device__ float g_q[M_*D_];
__device__ float g_k[M_*D_];
__device__ float g_v[M_*D_];
__device__ float g_ctx[M_*D_];
__device__ __nv_bfloat16 g_xs [M_*K2_];
__device__ __nv_bfloat16 g_cs [M_*K2_];
__device__ __nv_bfloat16 g_wqs[D_*K2_];   // weights, (hi,lo) interleaved
__device__ __nv_bfloat16 g_wks[D_*K2_];
__device__ __nv_bfloat16 g_wvs[D_*K2_];
__device__ __nv_bfloat16 g_wos[D_*K2_];
__device__ __nv_bfloat16 g_wqw[D_*K2_];   // weights, (lo,hi) swapped
__device__ __nv_bfloat16 g_wkw[D_*K2_];
__device__ __nv_bfloat16 g_wvw[D_*K2_];
__device__ __nv_bfloat16 g_wow[D_*K2_];
// attention split operands
__device__ __nv_bfloat16 g_qs [(size_t)B_*H_*L_*128];   // Q*scale (hi,lo)
__device__ __nv_bfloat16 g_qsw[(size_t)B_*H_*L_*128];   // Q*scale (lo,hi)
__device__ __nv_bfloat16 g_ks [(size_t)B_*H_*L_*128];   // K (hi,lo)
__device__ __nv_bfloat16 g_vs [(size_t)B_*H_*DH_*2*L_]; // V^T (hi,lo along key)

// ---------------- helpers ----------------
__device__ __forceinline__ uint32_t smem_u32(const void* p) {
    uint32_t a;
    asm("{ .reg .u64 t; cvta.to.shared.u64 t, %1; cvt.u32.u64 %0, t; }"
        : "=r"(a) : "l"(p));
    return a;
}
#define CP_ASYNC16(dst, src) \
    asm volatile("cp.async.cg.shared.global [%0], [%1], 16;" :: "r"(dst), "l"(src))
#define CP_COMMIT() asm volatile("cp.async.commit_group;" ::: "memory")
#define CP_WAIT(n)  asm volatile("cp.async.wait_group %0;" :: "n"(n) : "memory")

__device__ __forceinline__ uint32_t pack_hl(float x) {
    __nv_bfloat16 h = __float2bfloat16(x);
    __nv_bfloat16 l = __float2bfloat16(x - __bfloat162float(h));
    return (uint32_t)__bfloat16_as_ushort(h) |
           ((uint32_t)__bfloat16_as_ushort(l) << 16);
}
__device__ __forceinline__ uint32_t pack_lh(float x) {
    __nv_bfloat16 h = __float2bfloat16(x);
    __nv_bfloat16 l = __float2bfloat16(x - __bfloat162float(h));
    return (uint32_t)__bfloat16_as_ushort(l) |
           ((uint32_t)__bfloat16_as_ushort(h) << 16);
}

// ---------------- split kernels (projection inputs) ----------------
__global__ __launch_bounds__(256)
void split_act(const float* __restrict__ src_param, int src_tag, int dst_tag, int n4)
{
    const float* src = (src_tag == 0) ? src_param : g_ctx;
    __nv_bfloat16* dst = (dst_tag == 0) ? g_xs : g_cs;
    int i = blockIdx.x * 256 + threadIdx.x;
    if (i >= n4) return;
    float4 v = ((const float4*)src)[i];
    uint4 o;
    o.x = pack_hl(v.x); o.y = pack_hl(v.y); o.z = pack_hl(v.z); o.w = pack_hl(v.w);
    ((uint4*)dst)[i] = o;
}

__global__ __launch_bounds__(256)
void split_w(const float* __restrict__ src, int tag, int n4)
{
    __nv_bfloat16* dn = tag == 0 ? g_wqs : tag == 1 ? g_wks : tag == 2 ? g_wvs : g_wos;
    __nv_bfloat16* ds = tag == 0 ? g_wqw : tag == 1 ? g_wkw : tag == 2 ? g_wvw : g_wow;
    int i = blockIdx.x * 256 + threadIdx.x;
    if (i >= n4) return;
    float4 v = ((const float4*)src)[i];
    uint4 on, os;
    on.x = pack_hl(v.x); os.x = pack_lh(v.x);
    on.y = pack_hl(v.y); os.y = pack_lh(v.y);
    on.z = pack_hl(v.z); os.z = pack_lh(v.z);
    on.w = pack_hl(v.w); os.w = pack_lh(v.w);
    ((uint4*)dn)[i] = on;
    ((uint4*)ds)[i] = os;
}

// ---------------- attention operand preparation ----------------
__global__ __launch_bounds__(256)
void qk_split(int n4)   // n4 = M_*D_/4 (full [B,H,L,DH])
{
    int i = blockIdx.x * 256 + threadIdx.x;
    if (i >= n4) return;
    float4 v = ((const float4*)g_q)[i];
    uint4 on, ow;
    on.x = pack_hl(v.x * SCALE); ow.x = pack_lh(v.x * SCALE);
    on.y = pack_hl(v.y * SCALE); ow.y = pack_lh(v.y * SCALE);
    on.z = pack_hl(v.z * SCALE); ow.z = pack_lh(v.z * SCALE);
    on.w = pack_hl(v.w * SCALE); ow.w = pack_lh(v.w * SCALE);
    ((uint4*)g_qs)[i]  = on;
    ((uint4*)g_qsw)[i] = ow;
    v = ((const float4*)g_k)[i];
    on.x = pack_hl(v.x); on.y = pack_hl(v.y); on.z = pack_hl(v.z); on.w = pack_hl(v.w);
    ((uint4*)g_ks)[i] = on;
}

// V transpose + split along key: g_v [bh][l][d] -> g_vs [bh][d][2l]
__global__ __launch_bounds__(256)
void v_split()
{
    __shared__ float tile[128 * 65];
    const int lb = blockIdx.x;
    const int bh = blockIdx.y;
    const int tid = threadIdx.x;
    const float* src = g_v + ((size_t)bh * L_ + lb * 128) * DH_;
    for (int i = 0; i < 8; i++) {
        int u = tid + i * 256;
        int r = u >> 4, q = u & 15;
        float4 t = ((const float4*)(src + (size_t)r * DH_))[q];
        tile[r * 65 + q * 4 + 0] = t.x;
        tile[r * 65 + q * 4 + 1] = t.y;
        tile[r * 65 + q * 4 + 2] = t.z;
        tile[r * 65 + q * 4 + 3] = t.w;
    }
    __syncthreads();
    const int d = tid >> 2, part = tid & 3;
    uint32_t* dst = (uint32_t*)g_vs + ((size_t)bh * DH_ + d) * L_
                    + lb * 128 + part * 32;
    #pragma unroll
    for (int j = 0; j < 32; j++) {
        float val = tile[(part * 32 + j) * 65 + d];
        dst[j] = pack_hl(val);
    }
}

// ---------------- WMMA GEMM (projections) — cp.async pipelined, fused passes
#define TM 128
#define TN 128
#define BK 32
#define NCH (K2_ / BK)        // 64
#define AS 40
#define STG 20

__global__ __launch_bounds__(256)
void mma_gemm(int which,
              const float* __restrict__ bi0, const float* __restrict__ bi1,
              const float* __restrict__ bi2, float* __restrict__ out_dst)
{
    __shared__ __align__(16) __nv_bfloat16 sA [2][TM * AS];
    __shared__ __align__(16) __nv_bfloat16 sBn[2][TN * AS];
    __shared__ __align__(16) __nv_bfloat16 sBw[2][TN * AS];
    __shared__ __align__(16) float stage[8][16 * STG];

    const int mat = blockIdx.z;
    const __nv_bfloat16* A = (which == 0) ? g_xs : g_cs;
    const __nv_bfloat16* Bn =
        (which == 1) ? g_wos : (mat == 0 ? g_wqs : (mat == 1 ? g_wks : g_wvs));
    const __nv_bfloat16* Bw =
        (which == 1) ? g_wow : (mat == 0 ? g_wqw : (mat == 1 ? g_wkw : g_wvw));
    const float* bias = (mat == 0) ? bi0 : (mat == 1 ? bi1 : bi2);
    float* dsel = (mat == 0) ? g_q : (mat == 1 ? g_k : g_v);

    const int row0 = blockIdx.x * TM;
    const int col0 = blockIdx.y * TN;
    const int tid  = threadIdx.x;
    const int wid  = tid >> 5, lane = tid & 31;
    const int wr   = wid >> 2;
    const int wc   = wid & 3;

    wmma::fragment<wmma::accumulator, 16, 16, 16, float> acc[4][2];
    #pragma unroll
    for (int i = 0; i < 4; i++)
        #pragma unroll
        for (int j = 0; j < 2; j++)
            wmma::fill_fragment(acc[i][j], 0.0f);

    // cp.async distribution: rows r0c and r0c+64, 16B quad q0c
    const int r0c = tid >> 2, q0c = tid & 3;
    const int r1c = r0c + 64;

    const size_t gA0 = (size_t)(row0 + r0c) * K2_ + q0c * 8;
    const size_t gA1 = (size_t)(row0 + r1c) * K2_ + q0c * 8;
    const size_t gB0 = (size_t)(col0 + r0c) * K2_ + q0c * 8;
    const size_t gB1 = (size_t)(col0 + r1c) * K2_ + q0c * 8;

    uint32_t dA0[2], dA1[2], dN0[2], dN1[2], dW0[2], dW1[2];
    #pragma unroll
    for (int s = 0; s < 2; s++) {
        dA0[s] = smem_u32(&sA [s][r0c * AS + q0c * 8]);
        dA1[s] = smem_u32(&sA [s][r1c * AS + q0c * 8]);
        dN0[s] = smem_u32(&sBn[s][r0c * AS + q0c * 8]);
        dN1[s] = smem_u32(&sBn[s][r1c * AS + q0c * 8]);
        dW0[s] = smem_u32(&sBw[s][r0c * AS + q0c * 8]);
        dW1[s] = smem_u32(&sBw[s][r1c * AS + q0c * 8]);
    }

    // issue chunk 0
    {
        CP_ASYNC16(dA0[0], A  + gA0); CP_ASYNC16(dA1[0], A  + gA1);
        CP_ASYNC16(dN0[0], Bn + gB0); CP_ASYNC16(dN1[0], Bn + gB1);
        CP_ASYNC16(dW0[0], Bw + gB0); CP_ASYNC16(dW1[0], Bw + gB1);
        CP_COMMIT();
    }

    for (int ch = 0; ch < NCH; ch++) {
        const int st = ch & 1;
        if (ch + 1 < NCH) {
            const size_t ko = (size_t)(ch + 1) * BK;
            const int ns = st ^ 1;
            CP_ASYNC16(dA0[ns], A  + gA0 + ko); CP_ASYNC16(dA1[ns], A  + gA1 + ko);
            CP_ASYNC16(dN0[ns], Bn + gB0 + ko); CP_ASYNC16(dN1[ns], Bn + gB1 + ko);
            CP_ASYNC16(dW0[ns], Bw + gB0 + ko); CP_ASYNC16(dW1[ns], Bw + gB1 + ko);
            CP_COMMIT();
            CP_WAIT(1);
        } else {
            CP_WAIT(0);
        }
        __syncthreads();

        #pragma unroll
        for (int kk = 0; kk < 2; kk++) {
            const int k0 = kk * 16;
            wmma::fragment<wmma::matrix_a, 16, 16, 16, __nv_bfloat16,
                           wmma::row_major> af[4];
            #pragma unroll
            for (int i = 0; i < 4; i++)
                wmma::load_matrix_sync(af[i],
                    &sA[st][(wr * 64 + i * 16) * AS + k0], AS);
            wmma::fragment<wmma::matrix_b, 16, 16, 16, __nv_bfloat16,
                           wmma::col_major> bfn[2], bfw[2];
            #pragma unroll
            for (int j = 0; j < 2; j++) {
                wmma::load_matrix_sync(bfn[j],
                    &sBn[st][(wc * 32 + j * 16) * AS + k0], AS);
                wmma::load_matrix_sync(bfw[j],
                    &sBw[st][(wc * 32 + j * 16) * AS + k0], AS);
            }
            #pragma unroll
            for (int i = 0; i < 4; i++)
                #pragma unroll
                for (int j = 0; j < 2; j++) {
                    wmma::mma_sync(acc[i][j], af[i], bfn[j], acc[i][j]);
                    wmma::mma_sync(acc[i][j], af[i], bfw[j], acc[i][j]);
                }
        }
        __syncthreads();
    }

    // ---- epilogue ----
    #pragma unroll
    for (int i = 0; i < 4; i++) {
        #pragma unroll
        for (int j = 0; j < 2; j++) {
            wmma::store_matrix_sync(&stage[wid][0], acc[i][j], STG,
                                    wmma::mem_row_major);
            __syncwarp();
            #pragma unroll
            for (int e = 0; e < 8; e++) {
                int idx = lane * 8 + e;
                int rr = idx >> 4, cc = idx & 15;
                int m = row0 + wr * 64 + i * 16 + rr;
                int n = col0 + wc * 32 + j * 16 + cc;
                float v = stage[wid][rr * STG + cc] + bias[n];
                if (which == 1) {
                    out_dst[(size_t)m * D_ + n] = v;
                } else {
                    int l = m & (L_ - 1), bb = m >> 11;
                    int h = n >> 6, d = n & 63;
                    dsel[(((size_t)bb * H_ + h) * L_ + l) * DH_ + d] = v;
                }
            }
            __syncwarp();
        }
    }
}

// ---------------- WMMA attention ----------------
#define QB2  16
#define LD_S 2064
#define LD_K 136
#define LD_V 264
#define OFF_B    (QB2*LD_S*4)            // 132096
#define OFF_AN   (OFF_B + 34816)         // 166912
#define OFF_AW   (OFF_AN + 8448)         // 175360
#define OFF_RED  (OFF_AN + 16896)        // 183808
#define SM2_BYTES (OFF_RED + 8192)       // 192000

__global__ __launch_bounds__(256)
void attn_wmma(float* __restrict__ attn_out)
{
    extern __shared__ char smraw[];
    float* scr = (float*)smraw;                          // [16][LD_S]
    __nv_bfloat16* bB  = (__nv_bfloat16*)(smraw + OFF_B);
    __nv_bfloat16* bAn = (__nv_bfloat16*)(smraw + OFF_AN);
    __nv_bfloat16* bAw = (__nv_bfloat16*)(smraw + OFF_AW);
    float* red = (float*)(smraw + OFF_RED);
    const uint32_t bB_u32 = smem_u32(bB);

    const int q0 = blockIdx.x * QB2;
    const int hh = blockIdx.y, bb = blockIdx.z;
    const int tid = threadIdx.x, wid = tid >> 5, lane = tid & 31;
    const int bh = bb * H_ + hh;

    const __nv_bfloat16* Qn = g_qs  + ((size_t)bh * L_ + q0) * 128;
    const __nv_bfloat16* Qw = g_qsw + ((size_t)bh * L_ + q0) * 128;
    const __nv_bfloat16* Kh = g_ks  + (size_t)bh * L_ * 128;
    const __nv_bfloat16* Vt = g_vs  + (size_t)bh * DH_ * (2 * L_);

    // load Q tiles
    for (int u = tid; u < 512; u += 256) {
        int half = u >> 8;
        int v = u & 255;
        int r = v >> 4, q = v & 15;
        uint4 src = ((const uint4*)((half ? Qw : Qn) + r * 128))[q];
        __nv_bfloat16* dst = half ? bAw : bAn;
        *(uint4*)(dst + r * LD_K + q * 8) = src;
    }

    // ---- phase 1: scores ----
    {
        wmma::fragment<wmma::accumulator, 16, 16, 16, float> sacc;
        const int r_ld = tid >> 1, q_ld = tid & 1;   // 128 rows x 2 threads
        for (int kc = 0; kc < L_; kc += 128) {
            __syncthreads();
            // K chunk via cp.async: 2048 16B ops, 8 per thread
            #pragma unroll
            for (int i = 0; i < 8; i++) {
                int q = q_ld * 8 + i;                // 16 quads per row
                CP_ASYNC16(bB_u32 + (uint32_t)(r_ld * LD_K + q * 8) * 2,
                           Kh + (size_t)(kc + r_ld) * 128 + q * 8);
            }
            CP_COMMIT(); CP_WAIT(0);
            __syncthreads();
            wmma::fill_fragment(sacc, 0.0f);
            #pragma unroll
            for (int kt = 0; kt < 8; kt++) {
                wmma::fragment<wmma::matrix_a, 16, 16, 16, __nv_bfloat16,
                               wmma::row_major> a;
                wmma::fragment<wmma::matrix_b, 16, 16, 16, __nv_bfloat16,
                               wmma::col_major> b;
                wmma::load_matrix_sync(b, bB + (size_t)wid * 16 * LD_K + kt * 16, LD_K);
                wmma::load_matrix_sync(a, bAn + kt * 16, LD_K);
                wmma::mma_sync(sacc, a, b, sacc);
                wmma::load_matrix_sync(a, bAw + kt * 16, LD_K);
                wmma::mma_sync(sacc, a, b, sacc);
            }
            wmma::store_matrix_sync(scr + kc + wid * 16, sacc, LD_S,
                                    wmma::mem_row_major);
        }
    }
    __syncthreads();

    // ---- phase 2: softmax + write attention weights ----
    for (int r = wid; r < QB2; r += 8) {
        float* row = scr + (size_t)r * LD_S;
        float m = -1e30f;
        for (int k = lane; k < L_; k += 32) m = fmaxf(m, row[k]);
        #pragma unroll
        for (int o = 16; o; o >>= 1) m = fmaxf(m, __shfl_xor_sync(0xffffffffu, m, o));
        float s = 0.f;
        for (int k = lane; k < L_; k += 32) {
            float e = __expf(row[k] - m);
            row[k] = e;
            s += e;
        }
        #pragma unroll
        for (int o = 16; o; o >>= 1) s += __shfl_xor_sync(0xffffffffu, s, o);
        float inv = 1.f / s;
        float* g = attn_out + ((size_t)bh * L_ + q0 + r) * L_;
        for (int k = lane; k < L_; k += 32) {
            float w = row[k] * inv;
            row[k] = w;
            g[k] = w;
        }
    }

    // ---- phase 3: ctx = W @ V ----
    {
        wmma::fragment<wmma::accumulator, 16, 16, 16, float> cacc;
        wmma::fill_fragment(cacc, 0.0f);
        const int nt = wid >> 1, kh = wid & 1;
        const int wr2 = tid >> 4, wks = (tid & 15) * 8;
        const int r_ld = tid >> 2, q_ld = tid & 3;    // 64 rows x 4 threads
        for (int c = 0; c < 16; c++) {
            __syncthreads();
            // Vt chunk [64][256 bf16] via cp.async: 2048 16B ops, 8 per thread
            #pragma unroll
            for (int i = 0; i < 8; i++) {
                int q = q_ld * 8 + i;                 // 32 quads per row
                CP_ASYNC16(bB_u32 + (uint32_t)(r_ld * LD_V + q * 8) * 2,
                           Vt + (size_t)r_ld * (2 * L_) + c * 256 + q * 8);
            }
            CP_COMMIT();
            // W chunk -> bAn (hi,lo), bAw (lo,hi): 16 rows x 128 keys
            {
                const float* srow = scr + (size_t)wr2 * LD_S + c * 128 + wks;
                uint32_t* wn = (uint32_t*)bAn + wr2 * (LD_V / 2) + wks;
                uint32_t* ww = (uint32_t*)bAw + wr2 * (LD_V / 2) + wks;
                #pragma unroll
                for (int j = 0; j < 8; j++) {
                    float w = srow[j];
                    wn[j] = pack_hl(w);
                    ww[j] = pack_lh(w);
                }
            }
            CP_WAIT(0);
            __syncthreads();
            #pragma unroll
            for (int kt = 0; kt < 8; kt++) {
                int k0 = kh * 128 + kt * 16;
                wmma::fragment<wmma::matrix_a, 16, 16, 16, __nv_bfloat16,
                               wmma::row_major> a;
                wmma::fragment<wmma::matrix_b, 16, 16, 16, __nv_bfloat16,
                               wmma::col_major> b;
                wmma::load_matrix_sync(b, bB + (size_t)nt * 16 * LD_V + k0, LD_V);
                wmma::load_matrix_sync(a, bAn + k0, LD_V);
                wmma::mma_sync(cacc, a, b, cacc);
                wmma::load_matrix_sync(a, bAw + k0, LD_V);
                wmma::mma_sync(cacc, a, b, cacc);
            }
        }
        __syncthreads();
        wmma::store_matrix_sync(red + wid * 256, cacc, 16, wmma::mem_row_major);
        __syncthreads();
        for (int e = tid; e < 1024; e += 256) {
            int m = e >> 6, col = e & 63;
            int w0 = (col >> 4) << 1;
            float v = red[w0 * 256 + m * 16 + (col & 15)]
                    + red[(w0 + 1) * 256 + m * 16 + (col & 15)];
            g_ctx[((size_t)bb * L_ + q0 + m) * D_ + hh * 64 + col] = v;
        }
    }
}

// ---------------- launch ----------------
extern "C" void kernel_launch(void* const* d_in, const int* in_sizes, int n_in,
                              void* d_out, int out_size)
{
    const float* x  = (const float*)d_in[0];
    const float* Wq = (const float*)d_in[1];
    const float* bq = (const float*)d_in[2];
    const float* Wk = (const float*)d_in[3];
    const float* bk = (const float*)d_in[4];
    const float* Wv = (const float*)d_in[5];
    const float* bv = (const float*)d_in[6];
    const float* Wo = (const float*)d_in[7];
    const float* bo = (const float*)d_in[8];

    float* out  = (float*)d_out;                       // [B, L, D]
    float* attn = out + (size_t)M_ * D_;               // [B, H, L, L]

    cudaFuncSetAttribute(attn_wmma,
                         cudaFuncAttributeMaxDynamicSharedMemorySize, SM2_BYTES);

    // split projection inputs
    {
        int n4x = M_ * D_ / 4;
        int n4w = D_ * D_ / 4;
        split_act<<<(n4x + 255) / 256, 256>>>(x, 0, 0, n4x);
        split_w<<<(n4w + 255) / 256, 256>>>(Wq, 0, n4w);
        split_w<<<(n4w + 255) / 256, 256>>>(Wk, 1, n4w);
        split_w<<<(n4w + 255) / 256, 256>>>(Wv, 2, n4w);
        split_w<<<(n4w + 255) / 256, 256>>>(Wo, 3, n4w);
    }

    // QKV projections
    dim3 gq(M_ / TM, D_ / TN, 3);
    mma_gemm<<<gq, 256>>>(0, bq, bk, bv, nullptr);

    // prepare attention operands
    {
        int n4 = M_ * D_ / 4;
        qk_split<<<(n4 + 255) / 256, 256>>>(n4);
        dim3 gv(L_ / 128, B_ * H_);
        v_split<<<gv, 256>>>();
    }

    // attention (wmma, exact split)
    dim3 ga(L_ / QB2, H_, B_);
    attn_wmma<<<ga, 256, SM2_BYTES>>>(attn);

    // split ctx (device-resolved source), output projection
    {
        int n4c = M_ * D_ / 4;
        split_act<<<(n4c + 255) / 256, 256>>>(nullptr, 1, 1, n4c);
    }
    dim3 go(M_ / TM, D_ / TN, 1);
    mma_gemm<<<go, 256>>>(1, bo, bo, bo, out);
}

// round 12
// speedup vs baseline: 2.1042x; 2.1042x over previous
#include <cuda_runtime.h>
#include <cuda_bf16.h>
#include <mma.h>
#include <cstdint>

using namespace nvcuda;

#define B_   2
#define L_   2048
#define D_   1024
#define H_   16
#define DH_  64
#define M_   (B_*L_)          // 4096 rows
#define K2_  2048             // split-K (hi/lo interleaved)
#define SCALE 0.125f          // 1/sqrt(64)

// ---------------- scratch (static device memory; no allocs) ----------------
__device__ float g_q[M_*D_];
__device__ float g_k[M_*D_];
__device__ float g_v[M_*D_];
__device__ float g_ctx[M_*D_];
__device__ __nv_bfloat16 g_xs [M_*K2_];
__device__ __nv_bfloat16 g_cs [M_*K2_];
__device__ __nv_bfloat16 g_wqs[D_*K2_];   // weights, (hi,lo) interleaved
__device__ __nv_bfloat16 g_wks[D_*K2_];
__device__ __nv_bfloat16 g_wvs[D_*K2_];
__device__ __nv_bfloat16 g_wos[D_*K2_];
__device__ __nv_bfloat16 g_wqw[D_*K2_];   // weights, (lo,hi) swapped
__device__ __nv_bfloat16 g_wkw[D_*K2_];
__device__ __nv_bfloat16 g_wvw[D_*K2_];
__device__ __nv_bfloat16 g_wow[D_*K2_];
// attention split operands
__device__ __nv_bfloat16 g_qs [(size_t)B_*H_*L_*128];   // Q*scale (hi,lo)
__device__ __nv_bfloat16 g_qsw[(size_t)B_*H_*L_*128];   // Q*scale (lo,hi)
__device__ __nv_bfloat16 g_ks [(size_t)B_*H_*L_*128];   // K (hi,lo)
__device__ __nv_bfloat16 g_vs [(size_t)B_*H_*DH_*2*L_]; // V^T (hi,lo along key)

// ---------------- hi/lo bf16 pair packing ----------------
__device__ __forceinline__ uint32_t pack_hl(float x) {
    __nv_bfloat16 h = __float2bfloat16(x);
    __nv_bfloat16 l = __float2bfloat16(x - __bfloat162float(h));
    return (uint32_t)__bfloat16_as_ushort(h) |
           ((uint32_t)__bfloat16_as_ushort(l) << 16);
}
__device__ __forceinline__ uint32_t pack_lh(float x) {
    __nv_bfloat16 h = __float2bfloat16(x);
    __nv_bfloat16 l = __float2bfloat16(x - __bfloat162float(h));
    return (uint32_t)__bfloat16_as_ushort(l) |
           ((uint32_t)__bfloat16_as_ushort(h) << 16);
}

// ---------------- split kernels (projection inputs) ----------------
__global__ __launch_bounds__(256)
void split_act(const float* __restrict__ src_param, int src_tag, int dst_tag, int n4)
{
    const float* src = (src_tag == 0) ? src_param : g_ctx;
    __nv_bfloat16* dst = (dst_tag == 0) ? g_xs : g_cs;
    int i = blockIdx.x * 256 + threadIdx.x;
    if (i >= n4) return;
    float4 v = ((const float4*)src)[i];
    uint4 o;
    o.x = pack_hl(v.x); o.y = pack_hl(v.y); o.z = pack_hl(v.z); o.w = pack_hl(v.w);
    ((uint4*)dst)[i] = o;
}

__global__ __launch_bounds__(256)
void split_w(const float* __restrict__ src, int tag, int n4)
{
    __nv_bfloat16* dn = tag == 0 ? g_wqs : tag == 1 ? g_wks : tag == 2 ? g_wvs : g_wos;
    __nv_bfloat16* ds = tag == 0 ? g_wqw : tag == 1 ? g_wkw : tag == 2 ? g_wvw : g_wow;
    int i = blockIdx.x * 256 + threadIdx.x;
    if (i >= n4) return;
    float4 v = ((const float4*)src)[i];
    uint4 on, os;
    on.x = pack_hl(v.x); os.x = pack_lh(v.x);
    on.y = pack_hl(v.y); os.y = pack_lh(v.y);
    on.z = pack_hl(v.z); os.z = pack_lh(v.z);
    on.w = pack_hl(v.w); os.w = pack_lh(v.w);
    ((uint4*)dn)[i] = on;
    ((uint4*)ds)[i] = os;
}

// ---------------- attention operand preparation ----------------
__global__ __launch_bounds__(256)
void qk_split(int n4)   // n4 = M_*D_/4 (full [B,H,L,DH])
{
    int i = blockIdx.x * 256 + threadIdx.x;
    if (i >= n4) return;
    float4 v = ((const float4*)g_q)[i];
    uint4 on, ow;
    on.x = pack_hl(v.x * SCALE); ow.x = pack_lh(v.x * SCALE);
    on.y = pack_hl(v.y * SCALE); ow.y = pack_lh(v.y * SCALE);
    on.z = pack_hl(v.z * SCALE); ow.z = pack_lh(v.z * SCALE);
    on.w = pack_hl(v.w * SCALE); ow.w = pack_lh(v.w * SCALE);
    ((uint4*)g_qs)[i]  = on;
    ((uint4*)g_qsw)[i] = ow;
    v = ((const float4*)g_k)[i];
    on.x = pack_hl(v.x); on.y = pack_hl(v.y); on.z = pack_hl(v.z); on.w = pack_hl(v.w);
    ((uint4*)g_ks)[i] = on;
}

// V transpose + split along key: g_v [bh][l][d] -> g_vs [bh][d][2l]
__global__ __launch_bounds__(256)
void v_split()
{
    __shared__ float tile[128 * 65];
    const int lb = blockIdx.x;
    const int bh = blockIdx.y;
    const int tid = threadIdx.x;
    const float* src = g_v + ((size_t)bh * L_ + lb * 128) * DH_;
    for (int i = 0; i < 8; i++) {
        int u = tid + i * 256;
        int r = u >> 4, q = u & 15;
        float4 t = ((const float4*)(src + (size_t)r * DH_))[q];
        tile[r * 65 + q * 4 + 0] = t.x;
        tile[r * 65 + q * 4 + 1] = t.y;
        tile[r * 65 + q * 4 + 2] = t.z;
        tile[r * 65 + q * 4 + 3] = t.w;
    }
    __syncthreads();
    const int d = tid >> 2, part = tid & 3;
    uint32_t* dst = (uint32_t*)g_vs + ((size_t)bh * DH_ + d) * L_
                    + lb * 128 + part * 32;
    #pragma unroll
    for (int j = 0; j < 32; j++) {
        float val = tile[(part * 32 + j) * 65 + d];
        dst[j] = pack_hl(val);
    }
}

// ---------------- WMMA GEMM (projections) — fused passes, sync loads -------
#define TM 128
#define TN 128
#define BK 32
#define NCH (K2_ / BK)        // 64
#define AS 40
#define STG 20

__global__ __launch_bounds__(256)
void mma_gemm(int which,
              const float* __restrict__ bi0, const float* __restrict__ bi1,
              const float* __restrict__ bi2, float* __restrict__ out_dst)
{
    __shared__ __align__(16) __nv_bfloat16 sA [TM * AS];
    __shared__ __align__(16) __nv_bfloat16 sBn[TN * AS];
    __shared__ __align__(16) __nv_bfloat16 sBw[TN * AS];
    __shared__ __align__(16) float stage[8][16 * STG];

    const int mat = blockIdx.z;
    const __nv_bfloat16* A = (which == 0) ? g_xs : g_cs;
    const __nv_bfloat16* Bn =
        (which == 1) ? g_wos : (mat == 0 ? g_wqs : (mat == 1 ? g_wks : g_wvs));
    const __nv_bfloat16* Bw =
        (which == 1) ? g_wow : (mat == 0 ? g_wqw : (mat == 1 ? g_wkw : g_wvw));
    const float* bias = (mat == 0) ? bi0 : (mat == 1 ? bi1 : bi2);
    float* dsel = (mat == 0) ? g_q : (mat == 1 ? g_k : g_v);

    const int row0 = blockIdx.x * TM;
    const int col0 = blockIdx.y * TN;
    const int tid  = threadIdx.x;
    const int wid  = tid >> 5, lane = tid & 31;
    const int wr   = wid >> 2;
    const int wc   = wid & 3;

    wmma::fragment<wmma::accumulator, 16, 16, 16, float> acc[4][2];
    #pragma unroll
    for (int i = 0; i < 4; i++)
        #pragma unroll
        for (int j = 0; j < 2; j++)
            wmma::fill_fragment(acc[i][j], 0.0f);

    // tile-copy indices: 512 uint4 per operand tile, 2 per thread
    const int r0c = tid >> 2,          q0c = tid & 3;
    const int r1c = (tid + 256) >> 2,  q1c = (tid + 256) & 3;

    for (int ch = 0; ch < NCH; ch++) {
        const int k0g = ch * BK;
        __syncthreads();
        *(uint4*)&sA [r0c * AS + q0c * 8] =
            *(const uint4*)(A  + (size_t)(row0 + r0c) * K2_ + k0g + q0c * 8);
        *(uint4*)&sA [r1c * AS + q1c * 8] =
            *(const uint4*)(A  + (size_t)(row0 + r1c) * K2_ + k0g + q1c * 8);
        *(uint4*)&sBn[r0c * AS + q0c * 8] =
            *(const uint4*)(Bn + (size_t)(col0 + r0c) * K2_ + k0g + q0c * 8);
        *(uint4*)&sBn[r1c * AS + q1c * 8] =
            *(const uint4*)(Bn + (size_t)(col0 + r1c) * K2_ + k0g + q1c * 8);
        *(uint4*)&sBw[r0c * AS + q0c * 8] =
            *(const uint4*)(Bw + (size_t)(col0 + r0c) * K2_ + k0g + q0c * 8);
        *(uint4*)&sBw[r1c * AS + q1c * 8] =
            *(const uint4*)(Bw + (size_t)(col0 + r1c) * K2_ + k0g + q1c * 8);
        __syncthreads();

        #pragma unroll
        for (int kk = 0; kk < 2; kk++) {
            const int k0 = kk * 16;
            wmma::fragment<wmma::matrix_a, 16, 16, 16, __nv_bfloat16,
                           wmma::row_major> af[4];
            #pragma unroll
            for (int i = 0; i < 4; i++)
                wmma::load_matrix_sync(af[i], &sA[(wr * 64 + i * 16) * AS + k0], AS);
            wmma::fragment<wmma::matrix_b, 16, 16, 16, __nv_bfloat16,
                           wmma::col_major> bfn[2], bfw[2];
            #pragma unroll
            for (int j = 0; j < 2; j++) {
                wmma::load_matrix_sync(bfn[j], &sBn[(wc * 32 + j * 16) * AS + k0], AS);
                wmma::load_matrix_sync(bfw[j], &sBw[(wc * 32 + j * 16) * AS + k0], AS);
            }
            #pragma unroll
            for (int i = 0; i < 4; i++)
                #pragma unroll
                for (int j = 0; j < 2; j++) {
                    wmma::mma_sync(acc[i][j], af[i], bfn[j], acc[i][j]);
                    wmma::mma_sync(acc[i][j], af[i], bfw[j], acc[i][j]);
                }
        }
    }

    // ---- epilogue ----
    __syncthreads();
    #pragma unroll
    for (int i = 0; i < 4; i++) {
        #pragma unroll
        for (int j = 0; j < 2; j++) {
            wmma::store_matrix_sync(&stage[wid][0], acc[i][j], STG,
                                    wmma::mem_row_major);
            __syncwarp();
            #pragma unroll
            for (int e = 0; e < 8; e++) {
                int idx = lane * 8 + e;
                int rr = idx >> 4, cc = idx & 15;
                int m = row0 + wr * 64 + i * 16 + rr;
                int n = col0 + wc * 32 + j * 16 + cc;
                float v = stage[wid][rr * STG + cc] + bias[n];
                if (which == 1) {
                    out_dst[(size_t)m * D_ + n] = v;
                } else {
                    int l = m & (L_ - 1), bb = m >> 11;
                    int h = n >> 6, d = n & 63;
                    dsel[(((size_t)bb * H_ + h) * L_ + l) * DH_ + d] = v;
                }
            }
            __syncwarp();
        }
    }
}

// ---------------- WMMA attention — scores streamed through attn_out gmem ---
// smem: bB (K/Vt chunk) | bAn | bAw | red  = ~60KB -> 3 CTAs/SM
#define QB2  16
#define LD_K 136
#define LD_V 264
#define OFF_AN   34816
#define OFF_AW   (OFF_AN + 8448)         // 43264
#define OFF_RED  (OFF_AW + 8448)         // 51712
#define SM2_BYTES (OFF_RED + 8192)       // 59904

__global__ __launch_bounds__(256)
void attn_wmma(float* __restrict__ attn_out)
{
    extern __shared__ char smraw[];
    __nv_bfloat16* bB  = (__nv_bfloat16*)smraw;
    __nv_bfloat16* bAn = (__nv_bfloat16*)(smraw + OFF_AN);
    __nv_bfloat16* bAw = (__nv_bfloat16*)(smraw + OFF_AW);
    float* red = (float*)(smraw + OFF_RED);

    const int q0 = blockIdx.x * QB2;
    const int hh = blockIdx.y, bb = blockIdx.z;
    const int tid = threadIdx.x, wid = tid >> 5, lane = tid & 31;
    const int bh = bb * H_ + hh;

    const __nv_bfloat16* Qn = g_qs  + ((size_t)bh * L_ + q0) * 128;
    const __nv_bfloat16* Qw = g_qsw + ((size_t)bh * L_ + q0) * 128;
    const __nv_bfloat16* Kh = g_ks  + (size_t)bh * L_ * 128;
    const __nv_bfloat16* Vt = g_vs  + (size_t)bh * DH_ * (2 * L_);
    float* gW = attn_out + ((size_t)bh * L_ + q0) * L_;   // 16 x 2048 block

    // load Q tiles (16 x 128 bf16 each) into bAn/bAw, ldm LD_K
    for (int u = tid; u < 512; u += 256) {
        int half = u >> 8;
        int v = u & 255;
        int r = v >> 4, q = v & 15;
        uint4 src = ((const uint4*)((half ? Qw : Qn) + r * 128))[q];
        __nv_bfloat16* dst = half ? bAw : bAn;
        *(uint4*)(dst + r * LD_K + q * 8) = src;
    }

    // ---- phase 1: scores -> attn_out (raw) ----
    {
        wmma::fragment<wmma::accumulator, 16, 16, 16, float> sacc;
        for (int kc = 0; kc < L_; kc += 128) {
            __syncthreads();
            #pragma unroll
            for (int i = 0; i < 8; i++) {
                int u = tid + i * 256;           // 2048 uint4
                int r = u >> 4, q = u & 15;
                *(uint4*)(bB + r * LD_K + q * 8) =
                    ((const uint4*)(Kh + (size_t)(kc + r) * 128))[q];
            }
            __syncthreads();
            wmma::fill_fragment(sacc, 0.0f);
            #pragma unroll
            for (int kt = 0; kt < 8; kt++) {
                wmma::fragment<wmma::matrix_a, 16, 16, 16, __nv_bfloat16,
                               wmma::row_major> a;
                wmma::fragment<wmma::matrix_b, 16, 16, 16, __nv_bfloat16,
                               wmma::col_major> b;
                wmma::load_matrix_sync(b, bB + (size_t)wid * 16 * LD_K + kt * 16, LD_K);
                wmma::load_matrix_sync(a, bAn + kt * 16, LD_K);
                wmma::mma_sync(sacc, a, b, sacc);
                wmma::load_matrix_sync(a, bAw + kt * 16, LD_K);
                wmma::mma_sync(sacc, a, b, sacc);
            }
            wmma::store_matrix_sync(gW + kc + wid * 16, sacc, L_,
                                    wmma::mem_row_major);
        }
    }
    __syncthreads();

    // ---- phase 2: softmax in gmem (L2-hot) + final weights write ----
    for (int r = wid; r < QB2; r += 8) {
        float* row = gW + (size_t)r * L_;
        float m = -1e30f;
        for (int k = lane; k < L_; k += 32) m = fmaxf(m, row[k]);
        #pragma unroll
        for (int o = 16; o; o >>= 1) m = fmaxf(m, __shfl_xor_sync(0xffffffffu, m, o));
        float s = 0.f;
        for (int k = lane; k < L_; k += 32) {
            float e = __expf(row[k] - m);
            row[k] = e;
            s += e;
        }
        #pragma unroll
        for (int o = 16; o; o >>= 1) s += __shfl_xor_sync(0xffffffffu, s, o);
        float inv = 1.f / s;
        for (int k = lane; k < L_; k += 32)
            row[k] = row[k] * inv;
    }
    __syncthreads();

    // ---- phase 3: ctx = W @ V (weights re-read from gmem, L2-hot) ----
    {
        wmma::fragment<wmma::accumulator, 16, 16, 16, float> cacc;
        wmma::fill_fragment(cacc, 0.0f);
        const int nt = wid >> 1, kh = wid & 1;
        const int wr2 = tid >> 4, wks = (tid & 15) * 8;
        for (int c = 0; c < 16; c++) {               // 16 chunks x 128 keys
            __syncthreads();
            // Vt chunk [64][256 bf16] -> bB, ldm LD_V
            #pragma unroll
            for (int i = 0; i < 8; i++) {
                int u = tid + i * 256;               // 2048 uint4
                int r = u >> 5, q = u & 31;
                *(uint4*)(bB + r * LD_V + q * 8) =
                    ((const uint4*)(Vt + (size_t)r * (2 * L_) + c * 256))[q];
            }
            // W chunk (from gmem weights) -> bAn (hi,lo), bAw (lo,hi)
            {
                const float* srow = gW + (size_t)wr2 * L_ + c * 128 + wks;
                uint32_t* wn = (uint32_t*)bAn + wr2 * (LD_V / 2) + wks;
                uint32_t* ww = (uint32_t*)bAw + wr2 * (LD_V / 2) + wks;
                #pragma unroll
                for (int j = 0; j < 8; j++) {
                    float w = srow[j];
                    wn[j] = pack_hl(w);
                    ww[j] = pack_lh(w);
                }
            }
            __syncthreads();
            #pragma unroll
            for (int kt = 0; kt < 8; kt++) {
                int k0 = kh * 128 + kt * 16;
                wmma::fragment<wmma::matrix_a, 16, 16, 16, __nv_bfloat16,
                               wmma::row_major> a;
                wmma::fragment<wmma::matrix_b, 16, 16, 16, __nv_bfloat16,
                               wmma::col_major> b;
                wmma::load_matrix_sync(b, bB + (size_t)nt * 16 * LD_V + k0, LD_V);
                wmma::load_matrix_sync(a, bAn + k0, LD_V);
                wmma::mma_sync(cacc, a, b, cacc);
                wmma::load_matrix_sync(a, bAw + k0, LD_V);
                wmma::mma_sync(cacc, a, b, cacc);
            }
        }
        __syncthreads();
        wmma::store_matrix_sync(red + wid * 256, cacc, 16, wmma::mem_row_major);
        __syncthreads();
        for (int e = tid; e < 1024; e += 256) {
            int m = e >> 6, col = e & 63;
            int w0 = (col >> 4) << 1;
            float v = red[w0 * 256 + m * 16 + (col & 15)]
                    + red[(w0 + 1) * 256 + m * 16 + (col & 15)];
            g_ctx[((size_t)bb * L_ + q0 + m) * D_ + hh * 64 + col] = v;
        }
    }
}

// ---------------- launch ----------------
extern "C" void kernel_launch(void* const* d_in, const int* in_sizes, int n_in,
                              void* d_out, int out_size)
{
    const float* x  = (const float*)d_in[0];
    const float* Wq = (const float*)d_in[1];
    const float* bq = (const float*)d_in[2];
    const float* Wk = (const float*)d_in[3];
    const float* bk = (const float*)d_in[4];
    const float* Wv = (const float*)d_in[5];
    const float* bv = (const float*)d_in[6];
    const float* Wo = (const float*)d_in[7];
    const float* bo = (const float*)d_in[8];

    float* out  = (float*)d_out;                       // [B, L, D]
    float* attn = out + (size_t)M_ * D_;               // [B, H, L, L]

    cudaFuncSetAttribute(attn_wmma,
                         cudaFuncAttributeMaxDynamicSharedMemorySize, SM2_BYTES);

    // split projection inputs
    {
        int n4x = M_ * D_ / 4;
        int n4w = D_ * D_ / 4;
        split_act<<<(n4x + 255) / 256, 256>>>(x, 0, 0, n4x);
        split_w<<<(n4w + 255) / 256, 256>>>(Wq, 0, n4w);
        split_w<<<(n4w + 255) / 256, 256>>>(Wk, 1, n4w);
        split_w<<<(n4w + 255) / 256, 256>>>(Wv, 2, n4w);
        split_w<<<(n4w + 255) / 256, 256>>>(Wo, 3, n4w);
    }

    // QKV projections
    dim3 gq(M_ / TM, D_ / TN, 3);
    mma_gemm<<<gq, 256>>>(0, bq, bk, bv, nullptr);

    // prepare attention operands
    {
        int n4 = M_ * D_ / 4;
        qk_split<<<(n4 + 255) / 256, 256>>>(n4);
        dim3 gv(L_ / 128, B_ * H_);
        v_split<<<gv, 256>>>();
    }

    // attention (wmma, scores streamed via attn_out)
    dim3 ga(L_ / QB2, H_, B_);
    attn_wmma<<<ga, 256, SM2_BYTES>>>(attn);

    // split ctx (device-resolved source), output projection
    {
        int n4c = M_ * D_ / 4;
        split_act<<<(n4c + 255) / 256, 256>>>(nullptr, 1, 1, n4c);
    }
    dim3 go(M_ / TM, D_ / TN, 1);
    mma_gemm<<<go, 256>>>(1, bo, bo, bo, out);
}